// round 10
// baseline (speedup 1.0000x reference)
#include <cuda_runtime.h>
#include <cstdint>

// ============================================================================
// C[8192,4096] = X[8192,4096] @ W[4096,4096], fp32 in/out, tf32 mma.sync.
// R8 (2nd resubmit after infra failures): R7 shape (2 CTA/SM x 128 thr, warp
//     tile 64x64, 3-stage cp.async, crossbar demand 75%) + register
//     double-buffered fragments: LDSMs for k8-step ks+1 issue during the MMA
//     burst of step ks. Removes the serial ~90-cyc LDSM window that capped R7
//     at 75.9% tensor.
// ============================================================================
#define M_DIM 8192
#define K_DIM 4096
#define N_DIM 4096

#define BM 128
#define BN 128
#define BK 32                         // 32 floats = 128 B rows
#define STAGES 3
#define ITERS (K_DIM / BK)            // 128
#define NT (N_DIM / BN)               // 32
#define MT (M_DIM / BM)               // 64
#define THREADS 128

#define A_BYTES (BM * BK * 4)         // 16384
#define B_BYTES (BN * BK * 4)         // 16384
#define STAGE_BYTES (A_BYTES + B_BYTES)   // 32768
#define SMEM_TOTAL (STAGES * STAGE_BYTES) // 98304

__device__ float g_Bt[(size_t)N_DIM * K_DIM];   // 64 MB  (tf32-rounded W^T)
__device__ float g_Xr[(size_t)M_DIM * K_DIM];   // 128 MB (tf32-rounded X)

// ============================================================================
// PTX helpers
// ============================================================================
__device__ __forceinline__ uint32_t smem_to_u32(const void* p) {
    uint32_t a;
    asm("{ .reg .u64 t; cvta.to.shared.u64 t, %1; cvt.u32.u64 %0, t; }"
        : "=r"(a) : "l"(p));
    return a;
}

#define CP_ASYNC16(smem_addr, gptr) \
    asm volatile("cp.async.cg.shared.global [%0], [%1], 16;" \
                 :: "r"(smem_addr), "l"(gptr) : "memory")
#define CP_COMMIT() asm volatile("cp.async.commit_group;" ::: "memory")
#define CP_WAIT(n)  asm volatile("cp.async.wait_group %0;" :: "n"(n) : "memory")

#define LDSM_X4(r0, r1, r2, r3, addr) \
    asm volatile("ldmatrix.sync.aligned.m8n8.x4.shared.b16 {%0,%1,%2,%3}, [%4];" \
                 : "=r"(r0), "=r"(r1), "=r"(r2), "=r"(r3) : "r"(addr))

__device__ __forceinline__ float round_tf32(float x) {
    uint32_t u = __float_as_uint(x);
    asm("cvt.rna.tf32.f32 %0, %1;" : "=r"(u) : "r"(u));
    return __uint_as_float(u);
}

#define MMA_TF32(c, a, b) \
    asm volatile( \
        "mma.sync.aligned.m16n8k8.row.col.f32.tf32.tf32.f32 " \
        "{%0,%1,%2,%3}, {%4,%5,%6,%7}, {%8,%9}, {%0,%1,%2,%3};" \
        : "+f"((c)[0]), "+f"((c)[1]), "+f"((c)[2]), "+f"((c)[3]) \
        : "r"((a)[0]), "r"((a)[1]), "r"((a)[2]), "r"((a)[3]), \
          "r"((b)[0]), "r"((b)[1]))

// ============================================================================
// Kernel 0 (fused preprocessing): round X; transpose+round W
// ============================================================================
#define NXB ((M_DIM * (size_t)K_DIM / 4) / 256)      // 32768
#define NTB ((K_DIM / 32) * (N_DIM / 32))            // 16384

__global__ void __launch_bounds__(256) preprocess_kernel(
    const float* __restrict__ X, float* __restrict__ Xr,
    const float* __restrict__ W, float* __restrict__ Bt)
{
    __shared__ float t[32][33];
    unsigned bid = blockIdx.x;
    int tid = threadIdx.x;

    if (bid < NXB) {
        size_t i = (size_t)bid * 256 + tid;
        float4 v = ((const float4*)X)[i];
        v.x = round_tf32(v.x); v.y = round_tf32(v.y);
        v.z = round_tf32(v.z); v.w = round_tf32(v.w);
        ((float4*)Xr)[i] = v;
    } else {
        unsigned b2 = bid - NXB;
        int bx = (b2 % (N_DIM / 32)) * 32;   // n block
        int by = (b2 / (N_DIM / 32)) * 32;   // k block
        int tx = tid & 31, ty = tid >> 5;    // 32 x 8
        #pragma unroll
        for (int j = 0; j < 32; j += 8)
            t[ty + j][tx] = round_tf32(W[(size_t)(by + ty + j) * N_DIM + (bx + tx)]);
        __syncthreads();
        #pragma unroll
        for (int j = 0; j < 32; j += 8)
            Bt[(size_t)(bx + ty + j) * K_DIM + (by + tx)] = t[tx][ty + j];
    }
}

// ============================================================================
// Fragment load helpers (warp tile 64x64)
// ============================================================================
struct FragA { uint32_t r[4][4]; };   // 4 m-subtiles x 4 regs
struct FragB { uint32_t r[8][2]; };   // 8 n-subtiles x 2 regs

__device__ __forceinline__ void load_A(FragA& f, uint32_t aBase, uint32_t aoff) {
    #pragma unroll
    for (int mt = 0; mt < 4; mt++) {
        uint32_t addr = aBase + mt * 2048 + aoff;
        LDSM_X4(f.r[mt][0], f.r[mt][1], f.r[mt][2], f.r[mt][3], addr);
    }
}
__device__ __forceinline__ void load_B(FragB& f, uint32_t bBase, uint32_t boff) {
    #pragma unroll
    for (int j = 0; j < 4; j++) {
        uint32_t addr = bBase + j * 2048 + boff;
        uint32_t r0, r1, r2, r3;
        LDSM_X4(r0, r1, r2, r3, addr);
        f.r[2 * j][0] = r0;      f.r[2 * j][1] = r1;
        f.r[2 * j + 1][0] = r2;  f.r[2 * j + 1][1] = r3;
    }
}

// ============================================================================
// Kernel 1: tf32 mma.sync GEMM, reg-double-buffered fragments
//   128 threads = 4 warps (2m x 2n), warp tile 64x64, 3-stage, 2 CTAs/SM
// ============================================================================
__global__ void __launch_bounds__(THREADS, 2) gemm_tf32_kernel(
    const float* __restrict__ X,
    const float* __restrict__ Bt,
    float* __restrict__ C)
{
    extern __shared__ __align__(1024) char smem[];
    uint32_t sb = smem_to_u32(smem);

    int tid  = threadIdx.x;
    int wid  = tid >> 5;
    int lane = tid & 31;
    int bid  = blockIdx.x;
    int tn   = bid % NT;
    int tm   = bid / NT;

    int wm = wid & 1;
    int wn = wid >> 1;
    int warp_m0 = wm * 64;
    int warp_n0 = wn * 64;

    // ---- cp.async precompute (8 chunks of 16B per operand per thread) ----
    uint32_t off[8];
    uint32_t gA[8], gB[8];
    #pragma unroll
    for (int p = 0; p < 8; p++) {
        int ca = tid + p * THREADS;
        int row = ca >> 3, c = ca & 7;
        off[p] = row * 128 + ((c ^ (row & 7)) << 4);
        gA[p] = (uint32_t)(tm * BM + row) * K_DIM + c * 4;
        gB[p] = (uint32_t)(tn * BN + row) * K_DIM + c * 4;
    }

    // ---- ldmatrix per-lane address components ----
    uint32_t a_sw  = lane & 7;
    uint32_t a_co  = lane >> 4;
    uint32_t aBaseRel = (uint32_t)(warp_m0 + (lane & 15)) * 128;
    uint32_t b_sw  = lane & 7;
    uint32_t b_ch  = (lane >> 3) & 1;
    uint32_t bBaseRel = (uint32_t)(warp_n0 + (lane & 7) + ((lane >> 4) << 3)) * 128;

    float acc[4][8][4];
    #pragma unroll
    for (int mt = 0; mt < 4; mt++)
        #pragma unroll
        for (int nt = 0; nt < 8; nt++)
            #pragma unroll
            for (int v = 0; v < 4; v++) acc[mt][nt][v] = 0.0f;

    // ---- prologue: fill 2 stages ----
    #pragma unroll
    for (int i = 0; i < STAGES - 1; i++) {
        uint32_t sA = sb + i * STAGE_BYTES;
        uint32_t sB = sA + A_BYTES;
        #pragma unroll
        for (int p = 0; p < 8; p++) { CP_ASYNC16(sA + off[p], X  + gA[p]); gA[p] += BK; }
        #pragma unroll
        for (int p = 0; p < 8; p++) { CP_ASYNC16(sB + off[p], Bt + gB[p]); gB[p] += BK; }
        CP_COMMIT();
    }

    int s_comp = 0;
    int s_load = STAGES - 1;

    FragA fa[2];
    FragB fb[2];

    // ---- main loop ----
    #pragma unroll 1
    for (int i = 0; i < ITERS; i++) {
        CP_WAIT(STAGES - 2);
        __syncthreads();

        if (i + STAGES - 1 < ITERS) {
            uint32_t sA = sb + s_load * STAGE_BYTES;
            uint32_t sB = sA + A_BYTES;
            #pragma unroll
            for (int p = 0; p < 8; p++) { CP_ASYNC16(sA + off[p], X  + gA[p]); gA[p] += BK; }
            #pragma unroll
            for (int p = 0; p < 8; p++) { CP_ASYNC16(sB + off[p], Bt + gB[p]); gB[p] += BK; }
        }
        CP_COMMIT();

        uint32_t As = sb + s_comp * STAGE_BYTES;
        uint32_t Bs = As + A_BYTES;
        uint32_t aBase = As + aBaseRel;
        uint32_t bBase = Bs + bBaseRel;

        // k8-step 0 fragments
        load_A(fa[0], aBase, ((a_co ^ a_sw) << 4));
        load_B(fb[0], bBase, ((b_ch ^ b_sw) << 4));

        #pragma unroll
        for (int ks = 0; ks < 4; ks++) {
            int cur = ks & 1;
            int nxt = cur ^ 1;
            if (ks < 3) {
                uint32_t aoff = ((((uint32_t)(ks + 1) * 2 + a_co) ^ a_sw) << 4);
                uint32_t boff = ((((uint32_t)(ks + 1) * 2 + b_ch) ^ b_sw) << 4);
                load_A(fa[nxt], aBase, aoff);
                load_B(fb[nxt], bBase, boff);
            }
            #pragma unroll
            for (int mt = 0; mt < 4; mt++)
                #pragma unroll
                for (int nt = 0; nt < 8; nt++)
                    MMA_TF32(acc[mt][nt], fa[cur].r[mt], fb[cur].r[nt]);
        }

        if (++s_comp == STAGES) s_comp = 0;
        if (++s_load == STAGES) s_load = 0;
    }

    // ---- epilogue: direct global stores (float2) ----
    int row0 = tm * BM + warp_m0 + (lane >> 2);
    int col0 = tn * BN + warp_n0 + (lane & 3) * 2;
    #pragma unroll
    for (int mt = 0; mt < 4; mt++) {
        #pragma unroll
        for (int nt = 0; nt < 8; nt++) {
            int r = row0 + mt * 16;
            int c = col0 + nt * 8;
            float2* d0 = (float2*)(C + (size_t)r * N_DIM + c);
            float2* d1 = (float2*)(C + (size_t)(r + 8) * N_DIM + c);
            *d0 = make_float2(acc[mt][nt][0], acc[mt][nt][1]);
            *d1 = make_float2(acc[mt][nt][2], acc[mt][nt][3]);
        }
    }
}

// ============================================================================
// Host launcher
// ============================================================================
extern "C" void kernel_launch(void* const* d_in, const int* in_sizes, int n_in,
                              void* d_out, int out_size)
{
    const float* X = (const float*)d_in[0];   // [8192, 4096]
    const float* W = (const float*)d_in[1];   // [4096, 4096]
    float* C = (float*)d_out;                 // [8192, 4096]

    void* bt_ptr = nullptr;
    cudaGetSymbolAddress(&bt_ptr, g_Bt);
    void* xr_ptr = nullptr;
    cudaGetSymbolAddress(&xr_ptr, g_Xr);

    preprocess_kernel<<<(unsigned)(NXB + NTB), 256>>>(
        X, (float*)xr_ptr, W, (float*)bt_ptr);

    cudaFuncSetAttribute(gemm_tf32_kernel,
                         cudaFuncAttributeMaxDynamicSharedMemorySize, SMEM_TOTAL);
    gemm_tf32_kernel<<<MT * NT, THREADS, SMEM_TOTAL>>>(
        (const float*)xr_ptr, (const float*)bt_ptr, C);
}

// round 12
// speedup vs baseline: 1.0558x; 1.0558x over previous
#include <cuda_runtime.h>
#include <cstdint>

// ============================================================================
// C[8192,4096] = X[8192,4096] @ W[4096,4096], fp32 in/out, tf32 mma.sync.
// R11: R6 GEMM verbatim (proven correct+fastest: BM=BN=128, 8 warps of 32x64,
//      3-stage cp.async with wait->sync->issue->compute ordering, 2 CTA/SM)
//      + fused preprocessing kernel (round X, transpose+round W) from R7.
//      R10's wait/barrier reorder is REVERTED: cp.async.wait_group is
//      per-thread, so the __syncthreads() must come AFTER the wait for other
//      threads' loads to be visible (R10 raced, rel_err 7.4e-3).
// ============================================================================
#define M_DIM 8192
#define K_DIM 4096
#define N_DIM 4096

#define BM 128
#define BN 128
#define BK 32                         // 32 floats = 128 B rows
#define STAGES 3
#define ITERS (K_DIM / BK)            // 128
#define NT (N_DIM / BN)               // 32
#define MT (M_DIM / BM)               // 64
#define THREADS 256

#define A_BYTES (BM * BK * 4)         // 16384
#define B_BYTES (BN * BK * 4)         // 16384
#define STAGE_BYTES (A_BYTES + B_BYTES)   // 32768
#define SMEM_TOTAL (STAGES * STAGE_BYTES) // 98304

__device__ float g_Bt[(size_t)N_DIM * K_DIM];   // 64 MB  (tf32-rounded W^T)
__device__ float g_Xr[(size_t)M_DIM * K_DIM];   // 128 MB (tf32-rounded X)

// ============================================================================
// PTX helpers
// ============================================================================
__device__ __forceinline__ uint32_t smem_to_u32(const void* p) {
    uint32_t a;
    asm("{ .reg .u64 t; cvta.to.shared.u64 t, %1; cvt.u32.u64 %0, t; }"
        : "=r"(a) : "l"(p));
    return a;
}

#define CP_ASYNC16(smem_addr, gptr) \
    asm volatile("cp.async.cg.shared.global [%0], [%1], 16;" \
                 :: "r"(smem_addr), "l"(gptr) : "memory")
#define CP_COMMIT() asm volatile("cp.async.commit_group;" ::: "memory")
#define CP_WAIT(n)  asm volatile("cp.async.wait_group %0;" :: "n"(n) : "memory")

#define LDSM_X4(r0, r1, r2, r3, addr) \
    asm volatile("ldmatrix.sync.aligned.m8n8.x4.shared.b16 {%0,%1,%2,%3}, [%4];" \
                 : "=r"(r0), "=r"(r1), "=r"(r2), "=r"(r3) : "r"(addr))

__device__ __forceinline__ float round_tf32(float x) {
    uint32_t u = __float_as_uint(x);
    asm("cvt.rna.tf32.f32 %0, %1;" : "=r"(u) : "r"(u));
    return __uint_as_float(u);
}

#define MMA_TF32(c, a, b) \
    asm volatile( \
        "mma.sync.aligned.m16n8k8.row.col.f32.tf32.tf32.f32 " \
        "{%0,%1,%2,%3}, {%4,%5,%6,%7}, {%8,%9}, {%0,%1,%2,%3};" \
        : "+f"((c)[0]), "+f"((c)[1]), "+f"((c)[2]), "+f"((c)[3]) \
        : "r"((a)[0]), "r"((a)[1]), "r"((a)[2]), "r"((a)[3]), \
          "r"((b)[0]), "r"((b)[1]))

// ============================================================================
// Kernel 0 (fused preprocessing): round X -> Xr; transpose+round W -> Bt
// ============================================================================
#define NXB ((M_DIM * (size_t)K_DIM / 4) / 256)      // 32768
#define NTB ((K_DIM / 32) * (N_DIM / 32))            // 16384

__global__ void __launch_bounds__(256) preprocess_kernel(
    const float* __restrict__ X, float* __restrict__ Xr,
    const float* __restrict__ W, float* __restrict__ Bt)
{
    __shared__ float t[32][33];
    unsigned bid = blockIdx.x;
    int tid = threadIdx.x;

    if (bid < NXB) {
        size_t i = (size_t)bid * 256 + tid;
        float4 v = ((const float4*)X)[i];
        v.x = round_tf32(v.x); v.y = round_tf32(v.y);
        v.z = round_tf32(v.z); v.w = round_tf32(v.w);
        ((float4*)Xr)[i] = v;
    } else {
        unsigned b2 = bid - NXB;
        int bx = (b2 % (N_DIM / 32)) * 32;   // n block
        int by = (b2 / (N_DIM / 32)) * 32;   // k block
        int tx = tid & 31, ty = tid >> 5;    // 32 x 8
        #pragma unroll
        for (int j = 0; j < 32; j += 8)
            t[ty + j][tx] = round_tf32(W[(size_t)(by + ty + j) * N_DIM + (bx + tx)]);
        __syncthreads();
        #pragma unroll
        for (int j = 0; j < 32; j += 8)
            Bt[(size_t)(bx + ty + j) * K_DIM + (by + tx)] = t[tx][ty + j];
    }
}

// ============================================================================
// Kernel 1: tf32 mma.sync GEMM, 3-stage cp.async pipeline, 2 CTAs/SM
//   256 threads = 8 warps in 4(m) x 2(n); warp tile 32x64
//   Per-iter order (PROVEN): wait_group -> __syncthreads -> issue -> compute
// ============================================================================
__global__ void __launch_bounds__(THREADS, 2) gemm_tf32_kernel(
    const float* __restrict__ X,
    const float* __restrict__ Bt,
    float* __restrict__ C)
{
    extern __shared__ __align__(1024) char smem[];
    uint32_t sb = smem_to_u32(smem);

    int tid  = threadIdx.x;
    int wid  = tid >> 5;
    int lane = tid & 31;
    int bid  = blockIdx.x;
    int tn   = bid % NT;
    int tm   = bid / NT;

    int wm = wid & 3;              // m group 0..3
    int wn = wid >> 2;             // n group 0..1
    int warp_m0 = wm * 32;
    int warp_n0 = wn * 64;

    // ---- cp.async precompute (4 chunks of 16B per operand per thread) ----
    uint32_t offA[4]; const float* pA[4];
    uint32_t offB[4]; const float* pB[4];
    #pragma unroll
    for (int p = 0; p < 4; p++) {
        int ca = tid + p * THREADS;
        int row = ca >> 3, c = ca & 7;
        uint32_t off = row * 128 + ((c ^ (row & 7)) << 4);
        offA[p] = off;
        offB[p] = off;
        pA[p] = X  + (size_t)(tm * BM + row) * K_DIM + c * 4;
        pB[p] = Bt + (size_t)(tn * BN + row) * K_DIM + c * 4;
    }

    // ---- ldmatrix per-lane address components ----
    uint32_t a_rel = (uint32_t)(warp_m0 + (lane & 15)) * 128;
    uint32_t a_sw  = lane & 7;
    uint32_t a_co  = lane >> 4;
    uint32_t b_rel = (uint32_t)(warp_n0 + (lane & 7) + ((lane >> 4) << 3)) * 128;
    uint32_t b_sw  = lane & 7;
    uint32_t b_ch  = (lane >> 3) & 1;

    float acc[2][8][4];
    #pragma unroll
    for (int mt = 0; mt < 2; mt++)
        #pragma unroll
        for (int nt = 0; nt < 8; nt++)
            #pragma unroll
            for (int v = 0; v < 4; v++) acc[mt][nt][v] = 0.0f;

    // ---- prologue: fill 2 stages ----
    #pragma unroll
    for (int i = 0; i < STAGES - 1; i++) {
        uint32_t sA = sb + i * STAGE_BYTES;
        uint32_t sB = sA + A_BYTES;
        #pragma unroll
        for (int p = 0; p < 4; p++) { CP_ASYNC16(sA + offA[p], pA[p]); pA[p] += BK; }
        #pragma unroll
        for (int p = 0; p < 4; p++) { CP_ASYNC16(sB + offB[p], pB[p]); pB[p] += BK; }
        CP_COMMIT();
    }

    int s_comp = 0;              // stage computed this iter
    int s_load = STAGES - 1;     // stage filled this iter

    // ---- main loop ----
    #pragma unroll 1
    for (int i = 0; i < ITERS; i++) {
        CP_WAIT(STAGES - 2);     // own groups done => stage s_comp filled
        __syncthreads();         // all threads' waits passed => data visible;
                                 // also: all reads of stage s_load finished

        if (i + STAGES - 1 < ITERS) {
            uint32_t sA = sb + s_load * STAGE_BYTES;
            uint32_t sB = sA + A_BYTES;
            #pragma unroll
            for (int p = 0; p < 4; p++) { CP_ASYNC16(sA + offA[p], pA[p]); pA[p] += BK; }
            #pragma unroll
            for (int p = 0; p < 4; p++) { CP_ASYNC16(sB + offB[p], pB[p]); pB[p] += BK; }
        }
        CP_COMMIT();

        uint32_t As = sb + s_comp * STAGE_BYTES;
        uint32_t Bs = As + A_BYTES;
        uint32_t aBase = As + a_rel;
        uint32_t bBase = Bs + b_rel;

        #pragma unroll
        for (int ks = 0; ks < 4; ks++) {
            uint32_t a[2][4];
            #pragma unroll
            for (int mt = 0; mt < 2; mt++) {
                uint32_t addr = aBase + mt * 2048 +
                                ((((uint32_t)ks * 2 + a_co) ^ a_sw) << 4);
                LDSM_X4(a[mt][0], a[mt][1], a[mt][2], a[mt][3], addr);
            }
            uint32_t b[8][2];
            #pragma unroll
            for (int j = 0; j < 4; j++) {
                uint32_t addr = bBase + j * 2048 +
                                ((((uint32_t)ks * 2 + b_ch) ^ b_sw) << 4);
                uint32_t r0, r1, r2, r3;
                LDSM_X4(r0, r1, r2, r3, addr);
                b[2 * j][0] = r0;      b[2 * j][1] = r1;
                b[2 * j + 1][0] = r2;  b[2 * j + 1][1] = r3;
            }
            #pragma unroll
            for (int mt = 0; mt < 2; mt++)
                #pragma unroll
                for (int nt = 0; nt < 8; nt++)
                    MMA_TF32(acc[mt][nt], a[mt], b[nt]);
        }

        if (++s_comp == STAGES) s_comp = 0;
        if (++s_load == STAGES) s_load = 0;
    }

    // ---- epilogue: direct global stores (float2) ----
    int row0 = tm * BM + warp_m0 + (lane >> 2);
    int col0 = tn * BN + warp_n0 + (lane & 3) * 2;
    #pragma unroll
    for (int mt = 0; mt < 2; mt++) {
        #pragma unroll
        for (int nt = 0; nt < 8; nt++) {
            int r = row0 + mt * 16;
            int c = col0 + nt * 8;
            float2* d0 = (float2*)(C + (size_t)r * N_DIM + c);
            float2* d1 = (float2*)(C + (size_t)(r + 8) * N_DIM + c);
            *d0 = make_float2(acc[mt][nt][0], acc[mt][nt][1]);
            *d1 = make_float2(acc[mt][nt][2], acc[mt][nt][3]);
        }
    }
}

// ============================================================================
// Host launcher
// ============================================================================
extern "C" void kernel_launch(void* const* d_in, const int* in_sizes, int n_in,
                              void* d_out, int out_size)
{
    const float* X = (const float*)d_in[0];   // [8192, 4096]
    const float* W = (const float*)d_in[1];   // [4096, 4096]
    float* C = (float*)d_out;                 // [8192, 4096]

    void* bt_ptr = nullptr;
    cudaGetSymbolAddress(&bt_ptr, g_Bt);
    void* xr_ptr = nullptr;
    cudaGetSymbolAddress(&xr_ptr, g_Xr);

    preprocess_kernel<<<(unsigned)(NXB + NTB), 256>>>(
        X, (float*)xr_ptr, W, (float*)bt_ptr);

    cudaFuncSetAttribute(gemm_tf32_kernel,
                         cudaFuncAttributeMaxDynamicSharedMemorySize, SMEM_TOTAL);
    gemm_tf32_kernel<<<MT * NT, THREADS, SMEM_TOTAL>>>(
        (const float*)xr_ptr, (const float*)bt_ptr, C);
}

// round 13
// speedup vs baseline: 2.0094x; 1.9032x over previous
#include <cuda_runtime.h>
#include <cuda_fp16.h>
#include <cstdint>

// ============================================================================
// C[8192,4096] = X[8192,4096] @ W[4096,4096], fp32 in/out.
// R12: fp16 m16n8k16 mma.sync (fp32 accum). fp16 mantissa == tf32 mantissa
//      (10 bits) -> same rounding error as the passing tf32 kernel, but
//      2048 MACs/instr (2x) and 2B elements: ITERS 128->64, instr count
//      halved, smem traffic per MAC halved. Same pipeline skeleton as R11
//      (proven ordering: wait -> sync -> issue -> compute), 2 CTA/SM.
// ============================================================================
#define M_DIM 8192
#define K_DIM 4096
#define N_DIM 4096

#define BM 128
#define BN 128
#define BK 64                         // 64 halves = 128 B rows
#define STAGES 3
#define ITERS (K_DIM / BK)            // 64
#define NT (N_DIM / BN)               // 32
#define MT (M_DIM / BM)               // 64
#define THREADS 256

#define A_BYTES (BM * BK * 2)         // 16384
#define B_BYTES (BN * BK * 2)         // 16384
#define STAGE_BYTES (A_BYTES + B_BYTES)   // 32768
#define SMEM_TOTAL (STAGES * STAGE_BYTES) // 98304

__device__ __half g_Bth[(size_t)N_DIM * K_DIM];  // 32 MB (fp16 W^T, [N,K])
__device__ __half g_Xh [(size_t)M_DIM * K_DIM];  // 64 MB (fp16 X)

// ============================================================================
// PTX helpers
// ============================================================================
__device__ __forceinline__ uint32_t smem_to_u32(const void* p) {
    uint32_t a;
    asm("{ .reg .u64 t; cvta.to.shared.u64 t, %1; cvt.u32.u64 %0, t; }"
        : "=r"(a) : "l"(p));
    return a;
}

#define CP_ASYNC16(smem_addr, gptr) \
    asm volatile("cp.async.cg.shared.global [%0], [%1], 16;" \
                 :: "r"(smem_addr), "l"(gptr) : "memory")
#define CP_COMMIT() asm volatile("cp.async.commit_group;" ::: "memory")
#define CP_WAIT(n)  asm volatile("cp.async.wait_group %0;" :: "n"(n) : "memory")

#define LDSM_X4(r0, r1, r2, r3, addr) \
    asm volatile("ldmatrix.sync.aligned.m8n8.x4.shared.b16 {%0,%1,%2,%3}, [%4];" \
                 : "=r"(r0), "=r"(r1), "=r"(r2), "=r"(r3) : "r"(addr))

#define MMA_F16(c, a, b) \
    asm volatile( \
        "mma.sync.aligned.m16n8k16.row.col.f32.f16.f16.f32 " \
        "{%0,%1,%2,%3}, {%4,%5,%6,%7}, {%8,%9}, {%0,%1,%2,%3};" \
        : "+f"((c)[0]), "+f"((c)[1]), "+f"((c)[2]), "+f"((c)[3]) \
        : "r"((a)[0]), "r"((a)[1]), "r"((a)[2]), "r"((a)[3]), \
          "r"((b)[0]), "r"((b)[1]))

// ============================================================================
// Kernel 0 (fused preprocessing):
//   blocks [0, NXB): convert X -> fp16 (8 floats -> 8 halves per thread)
//   blocks [NXB, NXB+NTB): transpose W[k][n] -> fp16 Bt[n][k] (32x32 tiles)
// ============================================================================
#define NXB ((M_DIM * (size_t)K_DIM / 8) / 256)      // 16384
#define NTB ((K_DIM / 32) * (N_DIM / 32))            // 16384

__global__ void __launch_bounds__(256) preprocess_kernel(
    const float4* __restrict__ X, uint4* __restrict__ Xh,
    const float* __restrict__ W, __half* __restrict__ Bt)
{
    __shared__ float t[32][33];
    unsigned bid = blockIdx.x;
    int tid = threadIdx.x;

    if (bid < NXB) {
        size_t i = (size_t)bid * 256 + tid;
        float4 v0 = X[2 * i];
        float4 v1 = X[2 * i + 1];
        __half2 h0 = __floats2half2_rn(v0.x, v0.y);
        __half2 h1 = __floats2half2_rn(v0.z, v0.w);
        __half2 h2 = __floats2half2_rn(v1.x, v1.y);
        __half2 h3 = __floats2half2_rn(v1.z, v1.w);
        uint4 out;
        out.x = *(uint32_t*)&h0;  out.y = *(uint32_t*)&h1;
        out.z = *(uint32_t*)&h2;  out.w = *(uint32_t*)&h3;
        Xh[i] = out;
    } else {
        unsigned b2 = bid - NXB;
        int bx = (b2 % (N_DIM / 32)) * 32;   // n block
        int by = (b2 / (N_DIM / 32)) * 32;   // k block
        int tx = tid & 31, ty = tid >> 5;    // 32 x 8
        #pragma unroll
        for (int j = 0; j < 32; j += 8)
            t[ty + j][tx] = W[(size_t)(by + ty + j) * N_DIM + (bx + tx)];
        __syncthreads();
        #pragma unroll
        for (int j = 0; j < 32; j += 8)
            Bt[(size_t)(bx + ty + j) * K_DIM + (by + tx)] =
                __float2half_rn(t[tx][ty + j]);
    }
}

// ============================================================================
// Kernel 1: fp16 mma.sync GEMM, 3-stage cp.async pipeline, 2 CTAs/SM
//   256 threads = 8 warps in 4(m) x 2(n); warp tile 32x64
//   Per-iter order (PROVEN): wait_group -> __syncthreads -> issue -> compute
// ============================================================================
__global__ void __launch_bounds__(THREADS, 2) gemm_f16_kernel(
    const __half* __restrict__ X,
    const __half* __restrict__ Bt,
    float* __restrict__ C)
{
    extern __shared__ __align__(1024) char smem[];
    uint32_t sb = smem_to_u32(smem);

    int tid  = threadIdx.x;
    int wid  = tid >> 5;
    int lane = tid & 31;
    int bid  = blockIdx.x;
    int tn   = bid % NT;
    int tm   = bid / NT;

    int wm = wid & 3;              // m group 0..3
    int wn = wid >> 2;             // n group 0..1
    int warp_m0 = wm * 32;
    int warp_n0 = wn * 64;

    // ---- cp.async precompute (4 chunks of 16B per operand per thread) ----
    // 1024 chunks per operand per stage; row = 128B = 8 chunks of 8 halves.
    uint32_t offA[4]; const __half* pA[4];
    uint32_t offB[4]; const __half* pB[4];
    #pragma unroll
    for (int p = 0; p < 4; p++) {
        int ca = tid + p * THREADS;
        int row = ca >> 3, c = ca & 7;
        uint32_t off = row * 128 + ((c ^ (row & 7)) << 4);
        offA[p] = off;
        offB[p] = off;
        pA[p] = X  + (size_t)(tm * BM + row) * K_DIM + c * 8;
        pB[p] = Bt + (size_t)(tn * BN + row) * K_DIM + c * 8;
    }

    // ---- ldmatrix per-lane address components (identical geometry to tf32:
    //      chunk index = 2*ks + co; fp16 k16 = 32B = 2 chunks) ----
    uint32_t a_rel = (uint32_t)(warp_m0 + (lane & 15)) * 128;
    uint32_t a_sw  = lane & 7;
    uint32_t a_co  = lane >> 4;
    uint32_t b_rel = (uint32_t)(warp_n0 + (lane & 7) + ((lane >> 4) << 3)) * 128;
    uint32_t b_sw  = lane & 7;
    uint32_t b_ch  = (lane >> 3) & 1;

    float acc[2][8][4];
    #pragma unroll
    for (int mt = 0; mt < 2; mt++)
        #pragma unroll
        for (int nt = 0; nt < 8; nt++)
            #pragma unroll
            for (int v = 0; v < 4; v++) acc[mt][nt][v] = 0.0f;

    // ---- prologue: fill 2 stages ----
    #pragma unroll
    for (int i = 0; i < STAGES - 1; i++) {
        uint32_t sA = sb + i * STAGE_BYTES;
        uint32_t sB = sA + A_BYTES;
        #pragma unroll
        for (int p = 0; p < 4; p++) { CP_ASYNC16(sA + offA[p], pA[p]); pA[p] += BK; }
        #pragma unroll
        for (int p = 0; p < 4; p++) { CP_ASYNC16(sB + offB[p], pB[p]); pB[p] += BK; }
        CP_COMMIT();
    }

    int s_comp = 0;              // stage computed this iter
    int s_load = STAGES - 1;     // stage filled this iter

    // ---- main loop ----
    #pragma unroll 1
    for (int i = 0; i < ITERS; i++) {
        CP_WAIT(STAGES - 2);     // own groups done => stage s_comp filled
        __syncthreads();         // all threads' waits passed => data visible;
                                 // also: all reads of stage s_load finished

        if (i + STAGES - 1 < ITERS) {
            uint32_t sA = sb + s_load * STAGE_BYTES;
            uint32_t sB = sA + A_BYTES;
            #pragma unroll
            for (int p = 0; p < 4; p++) { CP_ASYNC16(sA + offA[p], pA[p]); pA[p] += BK; }
            #pragma unroll
            for (int p = 0; p < 4; p++) { CP_ASYNC16(sB + offB[p], pB[p]); pB[p] += BK; }
        }
        CP_COMMIT();

        uint32_t As = sb + s_comp * STAGE_BYTES;
        uint32_t Bs = As + A_BYTES;
        uint32_t aBase = As + a_rel;
        uint32_t bBase = Bs + b_rel;

        #pragma unroll
        for (int ks = 0; ks < 4; ks++) {       // 4 x k16 = BK 64 halves
            uint32_t a[2][4];
            #pragma unroll
            for (int mt = 0; mt < 2; mt++) {
                uint32_t addr = aBase + mt * 2048 +
                                ((((uint32_t)ks * 2 + a_co) ^ a_sw) << 4);
                LDSM_X4(a[mt][0], a[mt][1], a[mt][2], a[mt][3], addr);
            }
            uint32_t b[8][2];
            #pragma unroll
            for (int j = 0; j < 4; j++) {
                uint32_t addr = bBase + j * 2048 +
                                ((((uint32_t)ks * 2 + b_ch) ^ b_sw) << 4);
                uint32_t r0, r1, r2, r3;
                LDSM_X4(r0, r1, r2, r3, addr);
                b[2 * j][0] = r0;      b[2 * j][1] = r1;
                b[2 * j + 1][0] = r2;  b[2 * j + 1][1] = r3;
            }
            #pragma unroll
            for (int mt = 0; mt < 2; mt++)
                #pragma unroll
                for (int nt = 0; nt < 8; nt++)
                    MMA_F16(acc[mt][nt], a[mt], b[nt]);
        }

        if (++s_comp == STAGES) s_comp = 0;
        if (++s_load == STAGES) s_load = 0;
    }

    // ---- epilogue: direct global stores (float2) ----
    int row0 = tm * BM + warp_m0 + (lane >> 2);
    int col0 = tn * BN + warp_n0 + (lane & 3) * 2;
    #pragma unroll
    for (int mt = 0; mt < 2; mt++) {
        #pragma unroll
        for (int nt = 0; nt < 8; nt++) {
            int r = row0 + mt * 16;
            int c = col0 + nt * 8;
            float2* d0 = (float2*)(C + (size_t)r * N_DIM + c);
            float2* d1 = (float2*)(C + (size_t)(r + 8) * N_DIM + c);
            *d0 = make_float2(acc[mt][nt][0], acc[mt][nt][1]);
            *d1 = make_float2(acc[mt][nt][2], acc[mt][nt][3]);
        }
    }
}

// ============================================================================
// Host launcher
// ============================================================================
extern "C" void kernel_launch(void* const* d_in, const int* in_sizes, int n_in,
                              void* d_out, int out_size)
{
    const float* X = (const float*)d_in[0];   // [8192, 4096]
    const float* W = (const float*)d_in[1];   // [4096, 4096]
    float* C = (float*)d_out;                 // [8192, 4096]

    void* bt_ptr = nullptr;
    cudaGetSymbolAddress(&bt_ptr, g_Bth);
    void* xh_ptr = nullptr;
    cudaGetSymbolAddress(&xh_ptr, g_Xh);

    preprocess_kernel<<<(unsigned)(NXB + NTB), 256>>>(
        (const float4*)X, (uint4*)xh_ptr, W, (__half*)bt_ptr);

    cudaFuncSetAttribute(gemm_f16_kernel,
                         cudaFuncAttributeMaxDynamicSharedMemorySize, SMEM_TOTAL);
    gemm_f16_kernel<<<MT * NT, THREADS, SMEM_TOTAL>>>(
        (const __half*)xh_ptr, (const __half*)bt_ptr, C);
}